// round 15
// baseline (speedup 1.0000x reference)
#include <cuda_runtime.h>
#include <cuda_fp16.h>
#include <cstdint>
#include <math.h>

#define D_MODEL 1024
#define S_LEN   2048
#define BATCH   2
#define N_HEADS 16
#define HDIM    64
#define M_TOTAL (BATCH * S_LEN)   // 4096
#define DD ((size_t)D_MODEL * D_MODEL)

// ---------------- scratch (device globals; no allocation allowed) ----------
__device__ __half g_xh[(size_t)M_TOTAL * D_MODEL];
__device__ __half g_qh[(size_t)M_TOTAL * D_MODEL];
__device__ __half g_kh[(size_t)M_TOTAL * D_MODEL];
__device__ __half g_vh[(size_t)M_TOTAL * D_MODEL];
__device__ __half g_ctxh[(size_t)M_TOTAL * D_MODEL];
__device__ __half g_wth[4 * DD];   // WqT,WkT,WvT (contiguous [3072,1024]), WoT

// ================= helpers ================================================
__device__ __forceinline__ uint32_t smem_u32(const void* p) {
    uint32_t a;
    asm("{ .reg .u64 t; cvta.to.shared.u64 t, %1; cvt.u32.u64 %0, t; }" : "=r"(a) : "l"(p));
    return a;
}
__device__ __forceinline__ uint32_t pack_h2(float lo, float hi) {
    uint32_t r;
    asm("cvt.rn.f16x2.f32 %0, %1, %2;" : "=r"(r) : "f"(hi), "f"(lo));  // first src -> high
    return r;
}

#define CP_ASYNC16(sm32, gptr) \
    asm volatile("cp.async.cg.shared.global [%0], [%1], 16;" :: "r"(sm32), "l"(gptr) : "memory")
#define CP_COMMIT() asm volatile("cp.async.commit_group;" ::: "memory")
#define CP_WAIT(n)  asm volatile("cp.async.wait_group %0;" :: "n"(n) : "memory")

__device__ __forceinline__ void ldsm4(uint32_t* r, uint32_t addr) {
    asm volatile("ldmatrix.sync.aligned.m8n8.x4.shared.b16 {%0,%1,%2,%3}, [%4];"
                 : "=r"(r[0]), "=r"(r[1]), "=r"(r[2]), "=r"(r[3]) : "r"(addr));
}
__device__ __forceinline__ void ldsm4t(uint32_t* r, uint32_t addr) {
    asm volatile("ldmatrix.sync.aligned.m8n8.x4.trans.shared.b16 {%0,%1,%2,%3}, [%4];"
                 : "=r"(r[0]), "=r"(r[1]), "=r"(r[2]), "=r"(r[3]) : "r"(addr));
}
// D += A(16x16,row) * B(16x8,col)  f16 -> f32
__device__ __forceinline__ void mma_f16(float* d, const uint32_t* a, const uint32_t* b) {
    asm volatile(
        "mma.sync.aligned.m16n8k16.row.col.f32.f16.f16.f32 "
        "{%0,%1,%2,%3}, {%4,%5,%6,%7}, {%8,%9}, {%0,%1,%2,%3};"
        : "+f"(d[0]), "+f"(d[1]), "+f"(d[2]), "+f"(d[3])
        : "r"(a[0]), "r"(a[1]), "r"(a[2]), "r"(a[3]), "r"(b[0]), "r"(b[1]));
}

// ================= convert x -> fp16 ======================================
__global__ __launch_bounds__(256)
void round_x_kernel(const float* __restrict__ in, __half* __restrict__ out)
{
    size_t base = ((size_t)blockIdx.x * 256 + threadIdx.x) * 8;
    float4 a = *(const float4*)(in + base);
    float4 b = *(const float4*)(in + base + 4);
    uint4 o;
    o.x = pack_h2(a.x, a.y);
    o.y = pack_h2(a.z, a.w);
    o.z = pack_h2(b.x, b.y);
    o.w = pack_h2(b.z, b.w);
    *(uint4*)(out + base) = o;
}

// ========= transpose + convert: Wt[n][k] = h(W[k][n]) ======================
__global__ __launch_bounds__(256)
void transpose4_kernel(const float* __restrict__ w0, const float* __restrict__ w1,
                       const float* __restrict__ w2, const float* __restrict__ w3,
                       __half* __restrict__ out)
{
    __shared__ float t[32][33];
    const int z = blockIdx.z;
    const float* in = (z == 0) ? w0 : (z == 1) ? w1 : (z == 2) ? w2 : w3;
    __half* o = out + (size_t)z * DD;
    const int bx = blockIdx.x * 32, by = blockIdx.y * 32;
    const int x = threadIdx.x & 31;
    const int y0 = (threadIdx.x >> 5) * 4;
    #pragma unroll
    for (int j = 0; j < 4; j++)
        t[y0 + j][x] = in[(size_t)(by + y0 + j) * D_MODEL + bx + x];
    __syncthreads();
    #pragma unroll
    for (int j = 0; j < 4; j++)
        o[(size_t)(bx + y0 + j) * D_MODEL + by + x] = __float2half_rn(t[x][y0 + j]);
}

// ================= fp16 GEMM: C = A[M,K] @ Bt[N,K]^T + bias ================
// CTA 128x128, 8 warps (2m x 4n), warp tile 64x32, BK=32, 3-stage cp.async.
// smem row stride 40 halves (80B): ldmatrix conflict-free.
#define GA_STRB 80                         // bytes per 32-half row
#define GSTAGE_B (2 * 128 * GA_STRB)       // bytes per stage (A + B) = 20480
#define GEMM_SMEM_BYTES (3 * GSTAGE_B)     // 61440

__device__ __forceinline__ void gemm_load_chunk(
    const __half* __restrict__ A, const __half* __restrict__ Bt,
    int m0, int nrow0, int kc, uint32_t st32, int tid)
{
    #pragma unroll
    for (int p = 0; p < 2; p++) {
        int idx = tid + p * 256;           // 512 chunks A
        int r = idx >> 2, c = idx & 3;
        CP_ASYNC16(st32 + (uint32_t)(r * GA_STRB + c * 16),
                   A + (size_t)(m0 + r) * D_MODEL + kc * 32 + c * 8);
    }
    #pragma unroll
    for (int p = 0; p < 2; p++) {
        int idx = tid + p * 256;           // 512 chunks B
        int r = idx >> 2, c = idx & 3;
        CP_ASYNC16(st32 + (uint32_t)(128 * GA_STRB + r * GA_STRB + c * 16),
                   Bt + (size_t)(nrow0 + r) * D_MODEL + kc * 32 + c * 8);
    }
}

__device__ __forceinline__ void gemm_mainloop(
    const __half* __restrict__ A, const __half* __restrict__ Bt,
    int m0, int nrow0, uint32_t sbase, float acc[4][4][4])
{
    const int tid = threadIdx.x;
    const int lane = tid & 31;
    const int warp = tid >> 5;
    const int wm = (warp & 1) * 64;
    const int wn = (warp >> 1) * 32;
    const int l7 = lane & 7;
    const int lrow8 = (lane >> 3) & 1;
    const int lhi = lane >> 4;

    gemm_load_chunk(A, Bt, m0, nrow0, 0, sbase, tid);
    CP_COMMIT();
    gemm_load_chunk(A, Bt, m0, nrow0, 1, sbase + GSTAGE_B, tid);
    CP_COMMIT();

    int rs = 0, ws = 2;
    for (int i = 0; i < 32; i++) {
        if (i + 2 < 32)
            gemm_load_chunk(A, Bt, m0, nrow0, i + 2, sbase + (uint32_t)ws * GSTAGE_B, tid);
        CP_COMMIT();
        CP_WAIT(2);
        __syncthreads();

        const uint32_t as = sbase + (uint32_t)rs * GSTAGE_B;
        const uint32_t bs = as + 128 * GA_STRB;
        #pragma unroll
        for (int kk = 0; kk < 2; kk++) {
            uint32_t af[4][4], bf[2][4];
            #pragma unroll
            for (int mf = 0; mf < 4; mf++)
                ldsm4(af[mf], as + (uint32_t)((wm + mf * 16 + l7 + lrow8 * 8) * GA_STRB
                                              + kk * 32 + lhi * 16));
            #pragma unroll
            for (int nb = 0; nb < 2; nb++)
                ldsm4(bf[nb], bs + (uint32_t)((wn + nb * 16 + l7 + lhi * 8) * GA_STRB
                                              + kk * 32 + lrow8 * 16));
            #pragma unroll
            for (int mf = 0; mf < 4; mf++)
                #pragma unroll
                for (int nb = 0; nb < 2; nb++) {
                    mma_f16(acc[mf][2 * nb],     af[mf], bf[nb]);
                    mma_f16(acc[mf][2 * nb + 1], af[mf], bf[nb] + 2);
                }
        }
        __syncthreads();
        rs = (rs == 2) ? 0 : rs + 1;
        ws = (ws == 2) ? 0 : ws + 1;
    }
}

#define QSCALE (0.125f * 1.4426950408889634f)

// fused QKV projection: Bt = [WqT;WkT;WvT] as [3072,1024], half outputs
__global__ __launch_bounds__(256, 2)
void qkv_gemm_kernel(const __half* __restrict__ A, const __half* __restrict__ Bt,
                     const float* __restrict__ bq, const float* __restrict__ bk,
                     const float* __restrict__ bv,
                     __half* __restrict__ q, __half* __restrict__ k, __half* __restrict__ v)
{
    extern __shared__ char smraw[];
    const uint32_t sbase = smem_u32(smraw);
    const int sel = blockIdx.x >> 3;            // 0=q 1=k 2=v
    const int nrow0 = blockIdx.x * 128;
    const int n0 = (blockIdx.x & 7) * 128;
    const int m0 = blockIdx.y * 128;

    float acc[4][4][4];
    #pragma unroll
    for (int mf = 0; mf < 4; mf++)
        #pragma unroll
        for (int nf = 0; nf < 4; nf++)
            #pragma unroll
            for (int r = 0; r < 4; r++) acc[mf][nf][r] = 0.0f;

    gemm_mainloop(A, Bt, m0, nrow0, sbase, acc);

    const float* bias = (sel == 0) ? bq : (sel == 1) ? bk : bv;
    __half* C = (sel == 0) ? q : (sel == 1) ? k : v;
    const float esc = (sel == 0) ? QSCALE : 1.0f;

    const int lane = threadIdx.x & 31;
    const int warp = threadIdx.x >> 5;
    const int g = lane >> 2;
    const int t = lane & 3;
    const int wm = (warp & 1) * 64;
    const int wn = (warp >> 1) * 32;

    #pragma unroll
    for (int mf = 0; mf < 4; mf++) {
        #pragma unroll
        for (int h = 0; h < 2; h++) {
            const int row = m0 + wm + mf * 16 + g + h * 8;
            #pragma unroll
            for (int nf = 0; nf < 4; nf++) {
                const int col = n0 + wn + nf * 8 + 2 * t;
                float f0 = (acc[mf][nf][2 * h]     + bias[col])     * esc;
                float f1 = (acc[mf][nf][2 * h + 1] + bias[col + 1]) * esc;
                *(uint32_t*)(C + (size_t)row * D_MODEL + col) = pack_h2(f0, f1);
            }
        }
    }
}

// output projection: fp32 epilogue to d_out
__global__ __launch_bounds__(256, 2)
void out_gemm_kernel(const __half* __restrict__ A, const __half* __restrict__ Bt,
                     const float* __restrict__ bias, float* __restrict__ C)
{
    extern __shared__ char smraw[];
    const uint32_t sbase = smem_u32(smraw);
    const int nrow0 = blockIdx.x * 128;
    const int n0 = nrow0;
    const int m0 = blockIdx.y * 128;

    float acc[4][4][4];
    #pragma unroll
    for (int mf = 0; mf < 4; mf++)
        #pragma unroll
        for (int nf = 0; nf < 4; nf++)
            #pragma unroll
            for (int r = 0; r < 4; r++) acc[mf][nf][r] = 0.0f;

    gemm_mainloop(A, Bt, m0, nrow0, sbase, acc);

    const int lane = threadIdx.x & 31;
    const int warp = threadIdx.x >> 5;
    const int g = lane >> 2;
    const int t = lane & 3;
    const int wm = (warp & 1) * 64;
    const int wn = (warp >> 1) * 32;

    #pragma unroll
    for (int mf = 0; mf < 4; mf++) {
        #pragma unroll
        for (int h = 0; h < 2; h++) {
            const int row = m0 + wm + mf * 16 + g + h * 8;
            float* crow = C + (size_t)row * D_MODEL + n0 + wn;
            #pragma unroll
            for (int nf = 0; nf < 4; nf++) {
                const int col = nf * 8 + 2 * t;
                float2 o;
                o.x = acc[mf][nf][2 * h]     + bias[n0 + wn + col];
                o.y = acc[mf][nf][2 * h + 1] + bias[n0 + wn + col + 1];
                *(float2*)(crow + col) = o;
            }
        }
    }
}

// ================= flash attention (fp16 mma, register P) ==================
// CTA 64 q-rows, 4 warps x 16 rows, 64-key tiles, double-buffered K/V.
// 128 threads x 126 regs -> 4 CTAs/SM (decorrelated softmax phases).
#define ATHREADS 128
#define AK_STRB 144
#define ATILE_B (64 * AK_STRB)              // 9216 bytes
#define ATTN_SMEM_BYTES (4 * ATILE_B)       // 36864

__device__ __forceinline__ void attn_load_kv(
    const __half* __restrict__ K, const __half* __restrict__ V,
    size_t goff, uint32_t k32, uint32_t v32, int tid)
{
    #pragma unroll
    for (int p = 0; p < 4; p++) {
        int idx = tid + p * ATHREADS;       // 512 chunks each
        int r = idx >> 3, c = idx & 7;
        size_t go = goff + (size_t)r * D_MODEL + c * 8;
        CP_ASYNC16(k32 + (uint32_t)(r * AK_STRB + c * 16), K + go);
        CP_ASYNC16(v32 + (uint32_t)(r * AK_STRB + c * 16), V + go);
    }
}

__global__ __launch_bounds__(ATHREADS, 4)
void attn_mma_kernel(const __half* __restrict__ Q, const __half* __restrict__ K,
                     const __half* __restrict__ V, __half* __restrict__ Out)
{
    extern __shared__ char smraw[];
    const uint32_t sbase = smem_u32(smraw);

    const int tid = threadIdx.x;
    const int lane = tid & 31;
    const int warp = tid >> 5;            // 0..3
    const int g = lane >> 2;
    const int t = lane & 3;
    const int l7 = lane & 7;
    const int lm1 = (lane >> 3) & 1;
    const int lhi = lane >> 4;
    const int q0 = blockIdx.x * 64;
    const size_t hoff = (size_t)blockIdx.y * HDIM;
    const size_t boff = (size_t)blockIdx.z * S_LEN * D_MODEL;

    // Q fragments from global (pre-scaled by QSCALE in qkv epilogue)
    uint32_t qa[4][4];
    {
        const __half* qp = Q + boff + (size_t)(q0 + warp * 16 + g) * D_MODEL + hoff;
        const __half* q8 = qp + 8 * D_MODEL;
        #pragma unroll
        for (int ks = 0; ks < 4; ks++) {
            qa[ks][0] = *(const uint32_t*)(qp + ks * 16 + 2 * t);
            qa[ks][1] = *(const uint32_t*)(q8 + ks * 16 + 2 * t);
            qa[ks][2] = *(const uint32_t*)(qp + ks * 16 + 8 + 2 * t);
            qa[ks][3] = *(const uint32_t*)(q8 + ks * 16 + 8 + 2 * t);
        }
    }

    float o[8][4];
    #pragma unroll
    for (int nf = 0; nf < 8; nf++)
        #pragma unroll
        for (int r = 0; r < 4; r++) o[nf][r] = 0.0f;
    float mrun[2] = {-1e30f, -1e30f};
    float lrun[2] = {0.0f, 0.0f};

    attn_load_kv(K, V, boff + hoff, sbase, sbase + 2 * ATILE_B, tid);
    CP_COMMIT();

    for (int kt = 0; kt < 32; kt++) {
        const int s = kt & 1;
        if (kt + 1 < 32)
            attn_load_kv(K, V, boff + (size_t)(kt + 1) * 64 * D_MODEL + hoff,
                         sbase + (uint32_t)((s ^ 1)) * ATILE_B,
                         sbase + (uint32_t)(2 + (s ^ 1)) * ATILE_B, tid);
        CP_COMMIT();
        CP_WAIT(1);
        __syncthreads();

        const uint32_t kbs = sbase + (uint32_t)s * ATILE_B;
        const uint32_t vbs = sbase + (uint32_t)(2 + s) * ATILE_B;

        // S = Q * K^T : sc[nf] covers key cols nf*8..nf*8+7
        float sc[8][4];
        #pragma unroll
        for (int nf = 0; nf < 8; nf++)
            #pragma unroll
            for (int r = 0; r < 4; r++) sc[nf][r] = 0.0f;
        #pragma unroll
        for (int ks = 0; ks < 4; ks++) {            // d16 blocks
            #pragma unroll
            for (int nb = 0; nb < 4; nb++) {        // key n16 blocks
                uint32_t b[4];
                ldsm4(b, kbs + (uint32_t)((nb * 16 + l7 + lhi * 8) * AK_STRB
                                          + ks * 32 + lm1 * 16));
                mma_f16(sc[2 * nb],     qa[ks], b);
                mma_f16(sc[2 * nb + 1], qa[ks], b + 2);
            }
        }

        // online softmax per row-half; exponentials written back into sc
        #pragma unroll
        for (int h = 0; h < 2; h++) {
            float mx = mrun[h];
            #pragma unroll
            for (int nf = 0; nf < 8; nf++)
                mx = fmaxf(mx, fmaxf(sc[nf][2 * h], sc[nf][2 * h + 1]));
            mx = fmaxf(mx, __shfl_xor_sync(0xffffffffu, mx, 1));
            mx = fmaxf(mx, __shfl_xor_sync(0xffffffffu, mx, 2));
            float corr = exp2f(mrun[h] - mx);
            float rs = 0.0f;
            #pragma unroll
            for (int nf = 0; nf < 8; nf++) {
                float e0 = exp2f(sc[nf][2 * h] - mx);
                float e1 = exp2f(sc[nf][2 * h + 1] - mx);
                sc[nf][2 * h] = e0;
                sc[nf][2 * h + 1] = e1;
                rs += e0 + e1;
            }
            rs += __shfl_xor_sync(0xffffffffu, rs, 1);
            rs += __shfl_xor_sync(0xffffffffu, rs, 2);
            lrun[h] = lrun[h] * corr + rs;
            mrun[h] = mx;
            #pragma unroll
            for (int nf = 0; nf < 8; nf++) {
                o[nf][2 * h]     *= corr;
                o[nf][2 * h + 1] *= corr;
            }
        }

        // O += P * V : P fragments packed from sc in registers (no smem)
        #pragma unroll
        for (int ks = 0; ks < 4; ks++) {            // s16 blocks
            uint32_t pa[4];
            pa[0] = pack_h2(sc[2 * ks][0],     sc[2 * ks][1]);
            pa[1] = pack_h2(sc[2 * ks][2],     sc[2 * ks][3]);
            pa[2] = pack_h2(sc[2 * ks + 1][0], sc[2 * ks + 1][1]);
            pa[3] = pack_h2(sc[2 * ks + 1][2], sc[2 * ks + 1][3]);
            #pragma unroll
            for (int nb = 0; nb < 4; nb++) {        // d16 blocks
                uint32_t b[4];
                ldsm4t(b, vbs + (uint32_t)((ks * 16 + l7 + lm1 * 8) * AK_STRB
                                           + nb * 32 + lhi * 16));
                mma_f16(o[2 * nb],     pa, b);
                mma_f16(o[2 * nb + 1], pa, b + 2);
            }
        }
        __syncthreads();   // stage fully read before next prefetch overwrites
    }

    // epilogue: normalize, write ctx as half
    #pragma unroll
    for (int h = 0; h < 2; h++) {
        const int row = q0 + warp * 16 + g + 8 * h;
        const float inv = 1.0f / lrun[h];
        __half* op = Out + boff + (size_t)row * D_MODEL + hoff;
        #pragma unroll
        for (int nf = 0; nf < 8; nf++) {
            *(uint32_t*)(op + nf * 8 + 2 * t) =
                pack_h2(o[nf][2 * h] * inv, o[nf][2 * h + 1] * inv);
        }
    }
}

// ---------------- launch -------------------------------------------------
extern "C" void kernel_launch(void* const* d_in, const int* in_sizes, int n_in,
                              void* d_out, int out_size)
{
    const float* x  = (const float*)d_in[0];
    const float* Wq = (const float*)d_in[1];
    const float* bq = (const float*)d_in[2];
    const float* Wk = (const float*)d_in[3];
    const float* bk = (const float*)d_in[4];
    const float* Wv = (const float*)d_in[5];
    const float* bv = (const float*)d_in[6];
    const float* Wo = (const float*)d_in[7];
    const float* bo = (const float*)d_in[8];
    float* out = (float*)d_out;

    __half *xh, *qh, *kh, *vh, *ctxh, *wth;
    cudaGetSymbolAddress((void**)&xh,   g_xh);
    cudaGetSymbolAddress((void**)&qh,   g_qh);
    cudaGetSymbolAddress((void**)&kh,   g_kh);
    cudaGetSymbolAddress((void**)&vh,   g_vh);
    cudaGetSymbolAddress((void**)&ctxh, g_ctxh);
    cudaGetSymbolAddress((void**)&wth,  g_wth);

    cudaFuncSetAttribute(qkv_gemm_kernel, cudaFuncAttributeMaxDynamicSharedMemorySize, GEMM_SMEM_BYTES);
    cudaFuncSetAttribute(out_gemm_kernel, cudaFuncAttributeMaxDynamicSharedMemorySize, GEMM_SMEM_BYTES);
    cudaFuncSetAttribute(attn_mma_kernel, cudaFuncAttributeMaxDynamicSharedMemorySize, ATTN_SMEM_BYTES);

    round_x_kernel<<<(M_TOTAL * D_MODEL) / (256 * 8), 256>>>(x, xh);

    dim3 tgrid(D_MODEL / 32, D_MODEL / 32, 4);
    transpose4_kernel<<<tgrid, 256>>>(Wq, Wk, Wv, Wo, wth);

    dim3 qkvgrid(3 * D_MODEL / 128, M_TOTAL / 128);  // (24, 32)
    qkv_gemm_kernel<<<qkvgrid, 256, GEMM_SMEM_BYTES>>>(xh, wth, bq, bk, bv, qh, kh, vh);

    dim3 agrid(S_LEN / 64, N_HEADS, BATCH);          // (32, 16, 2)
    attn_mma_kernel<<<agrid, ATHREADS, ATTN_SMEM_BYTES>>>(qh, kh, vh, ctxh);

    dim3 ogrid(D_MODEL / 128, M_TOTAL / 128);        // (8, 32)
    out_gemm_kernel<<<ogrid, 256, GEMM_SMEM_BYTES>>>(ctxh, wth + 3 * DD, bo, out);
}

// round 16
// speedup vs baseline: 1.6071x; 1.6071x over previous
#include <cuda_runtime.h>
#include <cuda_fp16.h>
#include <cstdint>
#include <math.h>

#define D_MODEL 1024
#define S_LEN   2048
#define BATCH   2
#define N_HEADS 16
#define HDIM    64
#define M_TOTAL (BATCH * S_LEN)   // 4096
#define DD ((size_t)D_MODEL * D_MODEL)

// ---------------- scratch (device globals; no allocation allowed) ----------
__device__ __half g_xh[(size_t)M_TOTAL * D_MODEL];
__device__ __half g_qh[(size_t)M_TOTAL * D_MODEL];
__device__ __half g_kh[(size_t)M_TOTAL * D_MODEL];
__device__ __half g_vh[(size_t)M_TOTAL * D_MODEL];
__device__ __half g_ctxh[(size_t)M_TOTAL * D_MODEL];
__device__ __half g_wth[4 * DD];   // WqT,WkT,WvT (contiguous [3072,1024]), WoT

// ================= helpers ================================================
__device__ __forceinline__ uint32_t smem_u32(const void* p) {
    uint32_t a;
    asm("{ .reg .u64 t; cvta.to.shared.u64 t, %1; cvt.u32.u64 %0, t; }" : "=r"(a) : "l"(p));
    return a;
}
__device__ __forceinline__ uint32_t pack_h2(float lo, float hi) {
    uint32_t r;
    asm("cvt.rn.f16x2.f32 %0, %1, %2;" : "=r"(r) : "f"(hi), "f"(lo));  // first src -> high
    return r;
}

#define CP_ASYNC16(sm32, gptr) \
    asm volatile("cp.async.cg.shared.global [%0], [%1], 16;" :: "r"(sm32), "l"(gptr) : "memory")
#define CP_COMMIT() asm volatile("cp.async.commit_group;" ::: "memory")
#define CP_WAIT(n)  asm volatile("cp.async.wait_group %0;" :: "n"(n) : "memory")

__device__ __forceinline__ void ldsm4(uint32_t* r, uint32_t addr) {
    asm volatile("ldmatrix.sync.aligned.m8n8.x4.shared.b16 {%0,%1,%2,%3}, [%4];"
                 : "=r"(r[0]), "=r"(r[1]), "=r"(r[2]), "=r"(r[3]) : "r"(addr));
}
__device__ __forceinline__ void ldsm4t(uint32_t* r, uint32_t addr) {
    asm volatile("ldmatrix.sync.aligned.m8n8.x4.trans.shared.b16 {%0,%1,%2,%3}, [%4];"
                 : "=r"(r[0]), "=r"(r[1]), "=r"(r[2]), "=r"(r[3]) : "r"(addr));
}
// D += A(16x16,row) * B(16x8,col)  f16 -> f32
__device__ __forceinline__ void mma_f16(float* d, const uint32_t* a, const uint32_t* b) {
    asm volatile(
        "mma.sync.aligned.m16n8k16.row.col.f32.f16.f16.f32 "
        "{%0,%1,%2,%3}, {%4,%5,%6,%7}, {%8,%9}, {%0,%1,%2,%3};"
        : "+f"(d[0]), "+f"(d[1]), "+f"(d[2]), "+f"(d[3])
        : "r"(a[0]), "r"(a[1]), "r"(a[2]), "r"(a[3]), "r"(b[0]), "r"(b[1]));
}

// ================= convert x -> fp16 ======================================
__global__ __launch_bounds__(256)
void round_x_kernel(const float* __restrict__ in, __half* __restrict__ out)
{
    size_t base = ((size_t)blockIdx.x * 256 + threadIdx.x) * 8;
    float4 a = *(const float4*)(in + base);
    float4 b = *(const float4*)(in + base + 4);
    uint4 o;
    o.x = pack_h2(a.x, a.y);
    o.y = pack_h2(a.z, a.w);
    o.z = pack_h2(b.x, b.y);
    o.w = pack_h2(b.z, b.w);
    *(uint4*)(out + base) = o;
}

// ========= transpose + convert: Wt[n][k] = h(W[k][n]) ======================
__global__ __launch_bounds__(256)
void transpose4_kernel(const float* __restrict__ w0, const float* __restrict__ w1,
                       const float* __restrict__ w2, const float* __restrict__ w3,
                       __half* __restrict__ out)
{
    __shared__ float t[32][33];
    const int z = blockIdx.z;
    const float* in = (z == 0) ? w0 : (z == 1) ? w1 : (z == 2) ? w2 : w3;
    __half* o = out + (size_t)z * DD;
    const int bx = blockIdx.x * 32, by = blockIdx.y * 32;
    const int x = threadIdx.x & 31;
    const int y0 = (threadIdx.x >> 5) * 4;
    #pragma unroll
    for (int j = 0; j < 4; j++)
        t[y0 + j][x] = in[(size_t)(by + y0 + j) * D_MODEL + bx + x];
    __syncthreads();
    #pragma unroll
    for (int j = 0; j < 4; j++)
        o[(size_t)(bx + y0 + j) * D_MODEL + by + x] = __float2half_rn(t[x][y0 + j]);
}

// ================= fp16 GEMM: C = A[M,K] @ Bt[N,K]^T + bias ================
// CTA 128x128, 8 warps (2m x 4n), warp tile 64x32, BK=32.
// 4-stage cp.async pipeline, prefetch distance 2, ONE barrier per tile.
// smem row stride 40 halves (80B): ldmatrix conflict-free.
#define GA_STRB 80                         // bytes per 32-half row
#define GSTAGE_B (2 * 128 * GA_STRB)       // bytes per stage (A + B) = 20480
#define GEMM_SMEM_BYTES (4 * GSTAGE_B)     // 81920

__device__ __forceinline__ void gemm_load_chunk(
    const __half* __restrict__ A, const __half* __restrict__ Bt,
    int m0, int nrow0, int kc, uint32_t st32, int tid)
{
    #pragma unroll
    for (int p = 0; p < 2; p++) {
        int idx = tid + p * 256;           // 512 chunks A
        int r = idx >> 2, c = idx & 3;
        CP_ASYNC16(st32 + (uint32_t)(r * GA_STRB + c * 16),
                   A + (size_t)(m0 + r) * D_MODEL + kc * 32 + c * 8);
    }
    #pragma unroll
    for (int p = 0; p < 2; p++) {
        int idx = tid + p * 256;           // 512 chunks B
        int r = idx >> 2, c = idx & 3;
        CP_ASYNC16(st32 + (uint32_t)(128 * GA_STRB + r * GA_STRB + c * 16),
                   Bt + (size_t)(nrow0 + r) * D_MODEL + kc * 32 + c * 8);
    }
}

__device__ __forceinline__ void gemm_mainloop(
    const __half* __restrict__ A, const __half* __restrict__ Bt,
    int m0, int nrow0, uint32_t sbase, float acc[4][4][4])
{
    const int tid = threadIdx.x;
    const int lane = tid & 31;
    const int warp = tid >> 5;
    const int wm = (warp & 1) * 64;
    const int wn = (warp >> 1) * 32;
    const int l7 = lane & 7;
    const int lrow8 = (lane >> 3) & 1;
    const int lhi = lane >> 4;

    // prologue: stages 0,1 = chunks 0,1
    gemm_load_chunk(A, Bt, m0, nrow0, 0, sbase, tid);
    CP_COMMIT();
    gemm_load_chunk(A, Bt, m0, nrow0, 1, sbase + GSTAGE_B, tid);
    CP_COMMIT();

    for (int i = 0; i < 32; i++) {
        const int s = i & 3;
        // prefetch distance 2 into stage (i+2)&3 == (i-2)&3: safe, the barrier
        // below at iter i proves every warp finished compute of iter i-2.
        if (i + 2 < 32)
            gemm_load_chunk(A, Bt, m0, nrow0, i + 2,
                            sbase + (uint32_t)((i + 2) & 3) * GSTAGE_B, tid);
        CP_COMMIT();                       // unconditional: 1 group per iter
        CP_WAIT(2);                        // stage i&3 complete (own thread)
        __syncthreads();                   // all threads' stage data visible

        const uint32_t as = sbase + (uint32_t)s * GSTAGE_B;
        const uint32_t bs = as + 128 * GA_STRB;
        #pragma unroll
        for (int kk = 0; kk < 2; kk++) {
            uint32_t af[4][4], bf[2][4];
            #pragma unroll
            for (int mf = 0; mf < 4; mf++)
                ldsm4(af[mf], as + (uint32_t)((wm + mf * 16 + l7 + lrow8 * 8) * GA_STRB
                                              + kk * 32 + lhi * 16));
            #pragma unroll
            for (int nb = 0; nb < 2; nb++)
                ldsm4(bf[nb], bs + (uint32_t)((wn + nb * 16 + l7 + lhi * 8) * GA_STRB
                                              + kk * 32 + lrow8 * 16));
            #pragma unroll
            for (int mf = 0; mf < 4; mf++)
                #pragma unroll
                for (int nb = 0; nb < 2; nb++) {
                    mma_f16(acc[mf][2 * nb],     af[mf], bf[nb]);
                    mma_f16(acc[mf][2 * nb + 1], af[mf], bf[nb] + 2);
                }
        }
        // no trailing barrier: 4-stage + distance-2 prefetch makes it redundant
    }
}

#define QSCALE (0.125f * 1.4426950408889634f)

// fused QKV projection: Bt = [WqT;WkT;WvT] as [3072,1024], half outputs
__global__ __launch_bounds__(256, 2)
void qkv_gemm_kernel(const __half* __restrict__ A, const __half* __restrict__ Bt,
                     const float* __restrict__ bq, const float* __restrict__ bk,
                     const float* __restrict__ bv,
                     __half* __restrict__ q, __half* __restrict__ k, __half* __restrict__ v)
{
    extern __shared__ char smraw[];
    const uint32_t sbase = smem_u32(smraw);
    const int sel = blockIdx.x >> 3;            // 0=q 1=k 2=v
    const int nrow0 = blockIdx.x * 128;
    const int n0 = (blockIdx.x & 7) * 128;
    const int m0 = blockIdx.y * 128;

    float acc[4][4][4];
    #pragma unroll
    for (int mf = 0; mf < 4; mf++)
        #pragma unroll
        for (int nf = 0; nf < 4; nf++)
            #pragma unroll
            for (int r = 0; r < 4; r++) acc[mf][nf][r] = 0.0f;

    gemm_mainloop(A, Bt, m0, nrow0, sbase, acc);

    const float* bias = (sel == 0) ? bq : (sel == 1) ? bk : bv;
    __half* C = (sel == 0) ? q : (sel == 1) ? k : v;
    const float esc = (sel == 0) ? QSCALE : 1.0f;

    const int lane = threadIdx.x & 31;
    const int warp = threadIdx.x >> 5;
    const int g = lane >> 2;
    const int t = lane & 3;
    const int wm = (warp & 1) * 64;
    const int wn = (warp >> 1) * 32;

    #pragma unroll
    for (int mf = 0; mf < 4; mf++) {
        #pragma unroll
        for (int h = 0; h < 2; h++) {
            const int row = m0 + wm + mf * 16 + g + h * 8;
            #pragma unroll
            for (int nf = 0; nf < 4; nf++) {
                const int col = n0 + wn + nf * 8 + 2 * t;
                float f0 = (acc[mf][nf][2 * h]     + bias[col])     * esc;
                float f1 = (acc[mf][nf][2 * h + 1] + bias[col + 1]) * esc;
                *(uint32_t*)(C + (size_t)row * D_MODEL + col) = pack_h2(f0, f1);
            }
        }
    }
}

// output projection: fp32 epilogue to d_out
__global__ __launch_bounds__(256, 2)
void out_gemm_kernel(const __half* __restrict__ A, const __half* __restrict__ Bt,
                     const float* __restrict__ bias, float* __restrict__ C)
{
    extern __shared__ char smraw[];
    const uint32_t sbase = smem_u32(smraw);
    const int nrow0 = blockIdx.x * 128;
    const int n0 = nrow0;
    const int m0 = blockIdx.y * 128;

    float acc[4][4][4];
    #pragma unroll
    for (int mf = 0; mf < 4; mf++)
        #pragma unroll
        for (int nf = 0; nf < 4; nf++)
            #pragma unroll
            for (int r = 0; r < 4; r++) acc[mf][nf][r] = 0.0f;

    gemm_mainloop(A, Bt, m0, nrow0, sbase, acc);

    const int lane = threadIdx.x & 31;
    const int warp = threadIdx.x >> 5;
    const int g = lane >> 2;
    const int t = lane & 3;
    const int wm = (warp & 1) * 64;
    const int wn = (warp >> 1) * 32;

    #pragma unroll
    for (int mf = 0; mf < 4; mf++) {
        #pragma unroll
        for (int h = 0; h < 2; h++) {
            const int row = m0 + wm + mf * 16 + g + h * 8;
            float* crow = C + (size_t)row * D_MODEL + n0 + wn;
            #pragma unroll
            for (int nf = 0; nf < 4; nf++) {
                const int col = nf * 8 + 2 * t;
                float2 o;
                o.x = acc[mf][nf][2 * h]     + bias[n0 + wn + col];
                o.y = acc[mf][nf][2 * h + 1] + bias[n0 + wn + col + 1];
                *(float2*)(crow + col) = o;
            }
        }
    }
}

// ================= flash attention (fp16 mma, register P) ==================
// CTA 128 q-rows, 8 warps x 16 rows, 64-key tiles.
// 4-stage K/V pipeline, prefetch distance 2, ONE barrier per tile.
#define AK_STRB 144
#define ATILE_B (64 * AK_STRB)              // 9216 bytes
#define ATTN_SMEM_BYTES (8 * ATILE_B)       // 73728 (4 K stages + 4 V stages)

__device__ __forceinline__ void attn_load_kv(
    const __half* __restrict__ K, const __half* __restrict__ V,
    size_t goff, uint32_t k32, uint32_t v32, int tid)
{
    #pragma unroll
    for (int p = 0; p < 2; p++) {
        int idx = tid + p * 256;            // 512 chunks each
        int r = idx >> 3, c = idx & 7;
        size_t go = goff + (size_t)r * D_MODEL + c * 8;
        CP_ASYNC16(k32 + (uint32_t)(r * AK_STRB + c * 16), K + go);
        CP_ASYNC16(v32 + (uint32_t)(r * AK_STRB + c * 16), V + go);
    }
}

__global__ __launch_bounds__(256, 2)
void attn_mma_kernel(const __half* __restrict__ Q, const __half* __restrict__ K,
                     const __half* __restrict__ V, __half* __restrict__ Out)
{
    extern __shared__ char smraw[];
    const uint32_t sbase = smem_u32(smraw);

    const int tid = threadIdx.x;
    const int lane = tid & 31;
    const int warp = tid >> 5;
    const int g = lane >> 2;
    const int t = lane & 3;
    const int l7 = lane & 7;
    const int lm1 = (lane >> 3) & 1;
    const int lhi = lane >> 4;
    const int q0 = blockIdx.x * 128;
    const size_t hoff = (size_t)blockIdx.y * HDIM;
    const size_t boff = (size_t)blockIdx.z * S_LEN * D_MODEL;

    // Q fragments from global (pre-scaled by QSCALE in qkv epilogue)
    uint32_t qa[4][4];
    {
        const __half* qp = Q + boff + (size_t)(q0 + warp * 16 + g) * D_MODEL + hoff;
        const __half* q8 = qp + 8 * D_MODEL;
        #pragma unroll
        for (int ks = 0; ks < 4; ks++) {
            qa[ks][0] = *(const uint32_t*)(qp + ks * 16 + 2 * t);
            qa[ks][1] = *(const uint32_t*)(q8 + ks * 16 + 2 * t);
            qa[ks][2] = *(const uint32_t*)(qp + ks * 16 + 8 + 2 * t);
            qa[ks][3] = *(const uint32_t*)(q8 + ks * 16 + 8 + 2 * t);
        }
    }

    float o[8][4];
    #pragma unroll
    for (int nf = 0; nf < 8; nf++)
        #pragma unroll
        for (int r = 0; r < 4; r++) o[nf][r] = 0.0f;
    float mrun[2] = {-1e30f, -1e30f};
    float lrun[2] = {0.0f, 0.0f};

    // prologue: stages 0,1 = key tiles 0,1
    attn_load_kv(K, V, boff + hoff, sbase, sbase + 4 * ATILE_B, tid);
    CP_COMMIT();
    attn_load_kv(K, V, boff + (size_t)64 * D_MODEL + hoff,
                 sbase + ATILE_B, sbase + 5 * ATILE_B, tid);
    CP_COMMIT();

    for (int kt = 0; kt < 32; kt++) {
        const int s = kt & 3;
        // prefetch distance 2; overwrite of stage (kt-2)&3 is safe: the barrier
        // below at iter kt proves all warps finished compute of iter kt-2.
        if (kt + 2 < 32)
            attn_load_kv(K, V, boff + (size_t)(kt + 2) * 64 * D_MODEL + hoff,
                         sbase + (uint32_t)((kt + 2) & 3) * ATILE_B,
                         sbase + (uint32_t)(4 + ((kt + 2) & 3)) * ATILE_B, tid);
        CP_COMMIT();                        // unconditional: 1 group per iter
        CP_WAIT(2);                         // stage kt&3 complete (own thread)
        __syncthreads();                    // all threads' stage data visible

        const uint32_t kbs = sbase + (uint32_t)s * ATILE_B;
        const uint32_t vbs = sbase + (uint32_t)(4 + s) * ATILE_B;

        // S = Q * K^T : sc[nf] covers key cols nf*8..nf*8+7
        float sc[8][4];
        #pragma unroll
        for (int nf = 0; nf < 8; nf++)
            #pragma unroll
            for (int r = 0; r < 4; r++) sc[nf][r] = 0.0f;
        #pragma unroll
        for (int ks = 0; ks < 4; ks++) {            // d16 blocks
            #pragma unroll
            for (int nb = 0; nb < 4; nb++) {        // key n16 blocks
                uint32_t b[4];
                ldsm4(b, kbs + (uint32_t)((nb * 16 + l7 + lhi * 8) * AK_STRB
                                          + ks * 32 + lm1 * 16));
                mma_f16(sc[2 * nb],     qa[ks], b);
                mma_f16(sc[2 * nb + 1], qa[ks], b + 2);
            }
        }

        // online softmax per row-half; exponentials written back into sc
        #pragma unroll
        for (int h = 0; h < 2; h++) {
            float mx = mrun[h];
            #pragma unroll
            for (int nf = 0; nf < 8; nf++)
                mx = fmaxf(mx, fmaxf(sc[nf][2 * h], sc[nf][2 * h + 1]));
            mx = fmaxf(mx, __shfl_xor_sync(0xffffffffu, mx, 1));
            mx = fmaxf(mx, __shfl_xor_sync(0xffffffffu, mx, 2));
            float corr = exp2f(mrun[h] - mx);
            float rs = 0.0f;
            #pragma unroll
            for (int nf = 0; nf < 8; nf++) {
                float e0 = exp2f(sc[nf][2 * h] - mx);
                float e1 = exp2f(sc[nf][2 * h + 1] - mx);
                sc[nf][2 * h] = e0;
                sc[nf][2 * h + 1] = e1;
                rs += e0 + e1;
            }
            rs += __shfl_xor_sync(0xffffffffu, rs, 1);
            rs += __shfl_xor_sync(0xffffffffu, rs, 2);
            lrun[h] = lrun[h] * corr + rs;
            mrun[h] = mx;
            #pragma unroll
            for (int nf = 0; nf < 8; nf++) {
                o[nf][2 * h]     *= corr;
                o[nf][2 * h + 1] *= corr;
            }
        }

        // O += P * V : P fragments packed from sc in registers (no smem)
        #pragma unroll
        for (int ks = 0; ks < 4; ks++) {            // s16 blocks
            uint32_t pa[4];
            pa[0] = pack_h2(sc[2 * ks][0],     sc[2 * ks][1]);
            pa[1] = pack_h2(sc[2 * ks][2],     sc[2 * ks][3]);
            pa[2] = pack_h2(sc[2 * ks + 1][0], sc[2 * ks + 1][1]);
            pa[3] = pack_h2(sc[2 * ks + 1][2], sc[2 * ks + 1][3]);
            #pragma unroll
            for (int nb = 0; nb < 4; nb++) {        // d16 blocks
                uint32_t b[4];
                ldsm4t(b, vbs + (uint32_t)((ks * 16 + l7 + lm1 * 8) * AK_STRB
                                           + nb * 32 + lhi * 16));
                mma_f16(o[2 * nb],     pa, b);
                mma_f16(o[2 * nb + 1], pa, b + 2);
            }
        }
        // no trailing barrier: 4-stage + distance-2 prefetch makes it redundant
    }

    // epilogue: normalize, write ctx as half
    #pragma unroll
    for (int h = 0; h < 2; h++) {
        const int row = q0 + warp * 16 + g + 8 * h;
        const float inv = 1.0f / lrun[h];
        __half* op = Out + boff + (size_t)row * D_MODEL + hoff;
        #pragma unroll
        for (int nf = 0; nf < 8; nf++) {
            *(uint32_t*)(op + nf * 8 + 2 * t) =
                pack_h2(o[nf][2 * h] * inv, o[nf][2 * h + 1] * inv);
        }
    }
}

// ---------------- launch -------------------------------------------------
extern "C" void kernel_launch(void* const* d_in, const int* in_sizes, int n_in,
                              void* d_out, int out_size)
{
    const float* x  = (const float*)d_in[0];
    const float* Wq = (const float*)d_in[1];
    const float* bq = (const float*)d_in[2];
    const float* Wk = (const float*)d_in[3];
    const float* bk = (const float*)d_in[4];
    const float* Wv = (const float*)d_in[5];
    const float* bv = (const float*)d_in[6];
    const float* Wo = (const float*)d_in[7];
    const float* bo = (const float*)d_in[8];
    float* out = (float*)d_out;

    __half *xh, *qh, *kh, *vh, *ctxh, *wth;
    cudaGetSymbolAddress((void**)&xh,   g_xh);
    cudaGetSymbolAddress((void**)&qh,   g_qh);
    cudaGetSymbolAddress((void**)&kh,   g_kh);
    cudaGetSymbolAddress((void**)&vh,   g_vh);
    cudaGetSymbolAddress((void**)&ctxh, g_ctxh);
    cudaGetSymbolAddress((void**)&wth,  g_wth);

    cudaFuncSetAttribute(qkv_gemm_kernel, cudaFuncAttributeMaxDynamicSharedMemorySize, GEMM_SMEM_BYTES);
    cudaFuncSetAttribute(out_gemm_kernel, cudaFuncAttributeMaxDynamicSharedMemorySize, GEMM_SMEM_BYTES);
    cudaFuncSetAttribute(attn_mma_kernel, cudaFuncAttributeMaxDynamicSharedMemorySize, ATTN_SMEM_BYTES);

    round_x_kernel<<<(M_TOTAL * D_MODEL) / (256 * 8), 256>>>(x, xh);

    dim3 tgrid(D_MODEL / 32, D_MODEL / 32, 4);
    transpose4_kernel<<<tgrid, 256>>>(Wq, Wk, Wv, Wo, wth);

    dim3 qkvgrid(3 * D_MODEL / 128, M_TOTAL / 128);  // (24, 32)
    qkv_gemm_kernel<<<qkvgrid, 256, GEMM_SMEM_BYTES>>>(xh, wth, bq, bk, bv, qh, kh, vh);

    dim3 agrid(S_LEN / 128, N_HEADS, BATCH);         // (16, 16, 2)
    attn_mma_kernel<<<agrid, 256, ATTN_SMEM_BYTES>>>(qh, kh, vh, ctxh);

    dim3 ogrid(D_MODEL / 128, M_TOTAL / 128);        // (8, 32)
    out_gemm_kernel<<<ogrid, 256, GEMM_SMEM_BYTES>>>(ctxh, wth + 3 * DD, bo, out);
}

// round 17
// speedup vs baseline: 1.6557x; 1.0303x over previous
#include <cuda_runtime.h>
#include <cuda_fp16.h>
#include <cstdint>
#include <math.h>

#define D_MODEL 1024
#define S_LEN   2048
#define BATCH   2
#define N_HEADS 16
#define HDIM    64
#define M_TOTAL (BATCH * S_LEN)   // 4096
#define DD ((size_t)D_MODEL * D_MODEL)

// ---------------- scratch (device globals; no allocation allowed) ----------
__device__ __half g_xh[(size_t)M_TOTAL * D_MODEL];
__device__ __half g_qh[(size_t)M_TOTAL * D_MODEL];
__device__ __half g_kh[(size_t)M_TOTAL * D_MODEL];
__device__ __half g_vh[(size_t)M_TOTAL * D_MODEL];
__device__ __half g_ctxh[(size_t)M_TOTAL * D_MODEL];
__device__ __half g_wth[4 * DD];   // WqT,WkT,WvT (contiguous [3072,1024]), WoT

// ================= helpers ================================================
__device__ __forceinline__ uint32_t smem_u32(const void* p) {
    uint32_t a;
    asm("{ .reg .u64 t; cvta.to.shared.u64 t, %1; cvt.u32.u64 %0, t; }" : "=r"(a) : "l"(p));
    return a;
}
__device__ __forceinline__ uint32_t pack_h2(float lo, float hi) {
    uint32_t r;
    asm("cvt.rn.f16x2.f32 %0, %1, %2;" : "=r"(r) : "f"(hi), "f"(lo));  // first src -> high
    return r;
}
// single-instruction MUFU exponential (independent of fast-math flags)
__device__ __forceinline__ float ex2(float x) {
    float r;
    asm("ex2.approx.ftz.f32 %0, %1;" : "=f"(r) : "f"(x));
    return r;
}

#define CP_ASYNC16(sm32, gptr) \
    asm volatile("cp.async.cg.shared.global [%0], [%1], 16;" :: "r"(sm32), "l"(gptr) : "memory")
#define CP_COMMIT() asm volatile("cp.async.commit_group;" ::: "memory")
#define CP_WAIT(n)  asm volatile("cp.async.wait_group %0;" :: "n"(n) : "memory")

__device__ __forceinline__ void ldsm4(uint32_t* r, uint32_t addr) {
    asm volatile("ldmatrix.sync.aligned.m8n8.x4.shared.b16 {%0,%1,%2,%3}, [%4];"
                 : "=r"(r[0]), "=r"(r[1]), "=r"(r[2]), "=r"(r[3]) : "r"(addr));
}
__device__ __forceinline__ void ldsm4t(uint32_t* r, uint32_t addr) {
    asm volatile("ldmatrix.sync.aligned.m8n8.x4.trans.shared.b16 {%0,%1,%2,%3}, [%4];"
                 : "=r"(r[0]), "=r"(r[1]), "=r"(r[2]), "=r"(r[3]) : "r"(addr));
}
// D += A(16x16,row) * B(16x8,col)  f16 -> f32
__device__ __forceinline__ void mma_f16(float* d, const uint32_t* a, const uint32_t* b) {
    asm volatile(
        "mma.sync.aligned.m16n8k16.row.col.f32.f16.f16.f32 "
        "{%0,%1,%2,%3}, {%4,%5,%6,%7}, {%8,%9}, {%0,%1,%2,%3};"
        : "+f"(d[0]), "+f"(d[1]), "+f"(d[2]), "+f"(d[3])
        : "r"(a[0]), "r"(a[1]), "r"(a[2]), "r"(a[3]), "r"(b[0]), "r"(b[1]));
}

// ================= convert x -> fp16 ======================================
__global__ __launch_bounds__(256)
void round_x_kernel(const float* __restrict__ in, __half* __restrict__ out)
{
    size_t base = ((size_t)blockIdx.x * 256 + threadIdx.x) * 8;
    float4 a = *(const float4*)(in + base);
    float4 b = *(const float4*)(in + base + 4);
    uint4 o;
    o.x = pack_h2(a.x, a.y);
    o.y = pack_h2(a.z, a.w);
    o.z = pack_h2(b.x, b.y);
    o.w = pack_h2(b.z, b.w);
    *(uint4*)(out + base) = o;
}

// ========= transpose + convert: Wt[n][k] = h(W[k][n]) ======================
__global__ __launch_bounds__(256)
void transpose4_kernel(const float* __restrict__ w0, const float* __restrict__ w1,
                       const float* __restrict__ w2, const float* __restrict__ w3,
                       __half* __restrict__ out)
{
    __shared__ float t[32][33];
    const int z = blockIdx.z;
    const float* in = (z == 0) ? w0 : (z == 1) ? w1 : (z == 2) ? w2 : w3;
    __half* o = out + (size_t)z * DD;
    const int bx = blockIdx.x * 32, by = blockIdx.y * 32;
    const int x = threadIdx.x & 31;
    const int y0 = (threadIdx.x >> 5) * 4;
    #pragma unroll
    for (int j = 0; j < 4; j++)
        t[y0 + j][x] = in[(size_t)(by + y0 + j) * D_MODEL + bx + x];
    __syncthreads();
    #pragma unroll
    for (int j = 0; j < 4; j++)
        o[(size_t)(bx + y0 + j) * D_MODEL + by + x] = __float2half_rn(t[x][y0 + j]);
}

// ================= fp16 GEMM: C = A[M,K] @ Bt[N,K]^T + bias ================
// CTA 128x128, 8 warps (2m x 4n), warp tile 64x32, BK=32.
// 4-stage cp.async pipeline, prefetch distance 2, ONE barrier per tile,
// stage loop unrolled x4 (compile-time stage offsets).
#define GA_STRB 80                         // bytes per 32-half row
#define GSTAGE_B (2 * 128 * GA_STRB)       // bytes per stage (A + B) = 20480
#define GEMM_SMEM_BYTES (4 * GSTAGE_B)     // 81920

__device__ __forceinline__ void gemm_load_chunk(
    const __half* __restrict__ Ak, const __half* __restrict__ Bk,
    uint32_t st32, int tid)
{
    #pragma unroll
    for (int p = 0; p < 2; p++) {
        int idx = tid + p * 256;           // 512 chunks A
        int r = idx >> 2, c = idx & 3;
        CP_ASYNC16(st32 + (uint32_t)(r * GA_STRB + c * 16),
                   Ak + (size_t)r * D_MODEL + c * 8);
    }
    #pragma unroll
    for (int p = 0; p < 2; p++) {
        int idx = tid + p * 256;           // 512 chunks B
        int r = idx >> 2, c = idx & 3;
        CP_ASYNC16(st32 + (uint32_t)(128 * GA_STRB + r * GA_STRB + c * 16),
                   Bk + (size_t)r * D_MODEL + c * 8);
    }
}

__device__ __forceinline__ void gemm_mainloop(
    const __half* __restrict__ A, const __half* __restrict__ Bt,
    int m0, int nrow0, uint32_t sbase, float acc[4][4][4])
{
    const int tid = threadIdx.x;
    const int lane = tid & 31;
    const int warp = tid >> 5;
    const int wm = (warp & 1) * 64;
    const int wn = (warp >> 1) * 32;
    const int l7 = lane & 7;
    const int lrow8 = (lane >> 3) & 1;
    const int lhi = lane >> 4;

    // loop-invariant per-thread ldmatrix bases
    const uint32_t abase = sbase + (uint32_t)((wm + l7 + lrow8 * 8) * GA_STRB + lhi * 16);
    const uint32_t bbase = sbase + (uint32_t)(128 * GA_STRB
                                              + (wn + l7 + lhi * 8) * GA_STRB + lrow8 * 16);
    const __half* Ab = A + (size_t)m0 * D_MODEL;
    const __half* Bb = Bt + (size_t)nrow0 * D_MODEL;
    const __half* Apf = Ab;           // prefetch cursor (chunk i+2)
    const __half* Bpf = Bb;

    gemm_load_chunk(Apf, Bpf, sbase, tid);
    CP_COMMIT();
    gemm_load_chunk(Apf + 32, Bpf + 32, sbase + GSTAGE_B, tid);
    CP_COMMIT();
    Apf += 64; Bpf += 64;

    for (int i4 = 0; i4 < 8; i4++) {
        #pragma unroll
        for (int su = 0; su < 4; su++) {
            const int i = i4 * 4 + su;
            if (i + 2 < 32) {
                gemm_load_chunk(Apf, Bpf,
                                sbase + (uint32_t)(((su + 2) & 3)) * GSTAGE_B, tid);
                Apf += 32; Bpf += 32;
            }
            CP_COMMIT();
            CP_WAIT(2);
            __syncthreads();

            const uint32_t soff = (uint32_t)su * GSTAGE_B;
            #pragma unroll
            for (int kk = 0; kk < 2; kk++) {
                uint32_t af[4][4], bf[2][4];
                #pragma unroll
                for (int mf = 0; mf < 4; mf++)
                    ldsm4(af[mf], abase + soff + (uint32_t)(mf * 16 * GA_STRB + kk * 32));
                #pragma unroll
                for (int nb = 0; nb < 2; nb++)
                    ldsm4(bf[nb], bbase + soff + (uint32_t)(nb * 16 * GA_STRB + kk * 32));
                #pragma unroll
                for (int mf = 0; mf < 4; mf++)
                    #pragma unroll
                    for (int nb = 0; nb < 2; nb++) {
                        mma_f16(acc[mf][2 * nb],     af[mf], bf[nb]);
                        mma_f16(acc[mf][2 * nb + 1], af[mf], bf[nb] + 2);
                    }
            }
        }
    }
}

#define QSCALE (0.125f * 1.4426950408889634f)

// fused QKV projection: Bt = [WqT;WkT;WvT] as [3072,1024], half outputs
__global__ __launch_bounds__(256, 2)
void qkv_gemm_kernel(const __half* __restrict__ A, const __half* __restrict__ Bt,
                     const float* __restrict__ bq, const float* __restrict__ bk,
                     const float* __restrict__ bv,
                     __half* __restrict__ q, __half* __restrict__ k, __half* __restrict__ v)
{
    extern __shared__ char smraw[];
    const uint32_t sbase = smem_u32(smraw);
    const int sel = blockIdx.x >> 3;            // 0=q 1=k 2=v
    const int nrow0 = blockIdx.x * 128;
    const int n0 = (blockIdx.x & 7) * 128;
    const int m0 = blockIdx.y * 128;

    float acc[4][4][4];
    #pragma unroll
    for (int mf = 0; mf < 4; mf++)
        #pragma unroll
        for (int nf = 0; nf < 4; nf++)
            #pragma unroll
            for (int r = 0; r < 4; r++) acc[mf][nf][r] = 0.0f;

    gemm_mainloop(A, Bt, m0, nrow0, sbase, acc);

    const float* bias = (sel == 0) ? bq : (sel == 1) ? bk : bv;
    __half* C = (sel == 0) ? q : (sel == 1) ? k : v;
    const float esc = (sel == 0) ? QSCALE : 1.0f;

    const int lane = threadIdx.x & 31;
    const int warp = threadIdx.x >> 5;
    const int g = lane >> 2;
    const int t = lane & 3;
    const int wm = (warp & 1) * 64;
    const int wn = (warp >> 1) * 32;

    #pragma unroll
    for (int mf = 0; mf < 4; mf++) {
        #pragma unroll
        for (int h = 0; h < 2; h++) {
            const int row = m0 + wm + mf * 16 + g + h * 8;
            #pragma unroll
            for (int nf = 0; nf < 4; nf++) {
                const int col = n0 + wn + nf * 8 + 2 * t;
                float f0 = (acc[mf][nf][2 * h]     + bias[col])     * esc;
                float f1 = (acc[mf][nf][2 * h + 1] + bias[col + 1]) * esc;
                *(uint32_t*)(C + (size_t)row * D_MODEL + col) = pack_h2(f0, f1);
            }
        }
    }
}

// output projection: fp32 epilogue to d_out
__global__ __launch_bounds__(256, 2)
void out_gemm_kernel(const __half* __restrict__ A, const __half* __restrict__ Bt,
                     const float* __restrict__ bias, float* __restrict__ C)
{
    extern __shared__ char smraw[];
    const uint32_t sbase = smem_u32(smraw);
    const int nrow0 = blockIdx.x * 128;
    const int n0 = nrow0;
    const int m0 = blockIdx.y * 128;

    float acc[4][4][4];
    #pragma unroll
    for (int mf = 0; mf < 4; mf++)
        #pragma unroll
        for (int nf = 0; nf < 4; nf++)
            #pragma unroll
            for (int r = 0; r < 4; r++) acc[mf][nf][r] = 0.0f;

    gemm_mainloop(A, Bt, m0, nrow0, sbase, acc);

    const int lane = threadIdx.x & 31;
    const int warp = threadIdx.x >> 5;
    const int g = lane >> 2;
    const int t = lane & 3;
    const int wm = (warp & 1) * 64;
    const int wn = (warp >> 1) * 32;

    #pragma unroll
    for (int mf = 0; mf < 4; mf++) {
        #pragma unroll
        for (int h = 0; h < 2; h++) {
            const int row = m0 + wm + mf * 16 + g + h * 8;
            float* crow = C + (size_t)row * D_MODEL + n0 + wn;
            #pragma unroll
            for (int nf = 0; nf < 4; nf++) {
                const int col = nf * 8 + 2 * t;
                float2 o;
                o.x = acc[mf][nf][2 * h]     + bias[n0 + wn + col];
                o.y = acc[mf][nf][2 * h + 1] + bias[n0 + wn + col + 1];
                *(float2*)(crow + col) = o;
            }
        }
    }
}

// ================= flash attention (fp16 mma, register P) ==================
// CTA 128 q-rows, 8 warps x 16 rows, 64-key tiles.
// 4-stage K/V pipeline, prefetch distance 2, ONE barrier per tile,
// stage loop unrolled x4 (compile-time stage offsets, hoisted lane bases).
#define AK_STRB 144
#define ATILE_B (64 * AK_STRB)              // 9216 bytes
#define ATTN_SMEM_BYTES (8 * ATILE_B)       // 73728 (4 K stages + 4 V stages)

__device__ __forceinline__ void attn_load_kv(
    const __half* __restrict__ Kp, const __half* __restrict__ Vp,
    uint32_t k32, uint32_t v32, int tid)
{
    #pragma unroll
    for (int p = 0; p < 2; p++) {
        int idx = tid + p * 256;            // 512 chunks each
        int r = idx >> 3, c = idx & 7;
        size_t go = (size_t)r * D_MODEL + c * 8;
        CP_ASYNC16(k32 + (uint32_t)(r * AK_STRB + c * 16), Kp + go);
        CP_ASYNC16(v32 + (uint32_t)(r * AK_STRB + c * 16), Vp + go);
    }
}

__global__ __launch_bounds__(256, 2)
void attn_mma_kernel(const __half* __restrict__ Q, const __half* __restrict__ K,
                     const __half* __restrict__ V, __half* __restrict__ Out)
{
    extern __shared__ char smraw[];
    const uint32_t sbase = smem_u32(smraw);

    const int tid = threadIdx.x;
    const int lane = tid & 31;
    const int warp = tid >> 5;
    const int g = lane >> 2;
    const int t = lane & 3;
    const int l7 = lane & 7;
    const int lm1 = (lane >> 3) & 1;
    const int lhi = lane >> 4;
    const int q0 = blockIdx.x * 128;
    const size_t hoff = (size_t)blockIdx.y * HDIM;
    const size_t boff = (size_t)blockIdx.z * S_LEN * D_MODEL;

    // loop-invariant ldmatrix bases
    const uint32_t kbase = sbase + (uint32_t)((l7 + lhi * 8) * AK_STRB + lm1 * 16);
    const uint32_t vbase = sbase + (uint32_t)(4 * ATILE_B
                                              + (l7 + lm1 * 8) * AK_STRB + lhi * 16);

    // Q fragments from global (pre-scaled by QSCALE in qkv epilogue)
    uint32_t qa[4][4];
    {
        const __half* qp = Q + boff + (size_t)(q0 + warp * 16 + g) * D_MODEL + hoff;
        const __half* q8 = qp + 8 * D_MODEL;
        #pragma unroll
        for (int ks = 0; ks < 4; ks++) {
            qa[ks][0] = *(const uint32_t*)(qp + ks * 16 + 2 * t);
            qa[ks][1] = *(const uint32_t*)(q8 + ks * 16 + 2 * t);
            qa[ks][2] = *(const uint32_t*)(qp + ks * 16 + 8 + 2 * t);
            qa[ks][3] = *(const uint32_t*)(q8 + ks * 16 + 8 + 2 * t);
        }
    }

    float o[8][4];
    #pragma unroll
    for (int nf = 0; nf < 8; nf++)
        #pragma unroll
        for (int r = 0; r < 4; r++) o[nf][r] = 0.0f;
    float mrun[2] = {-1e30f, -1e30f};
    float lrun[2] = {0.0f, 0.0f};

    // prologue: stages 0,1 = key tiles 0,1
    const __half* kv0 = K + boff + hoff;
    const __half* vv0 = V + boff + hoff;
    attn_load_kv(kv0, vv0, sbase, sbase + 4 * ATILE_B, tid);
    CP_COMMIT();
    attn_load_kv(kv0 + (size_t)64 * D_MODEL, vv0 + (size_t)64 * D_MODEL,
                 sbase + ATILE_B, sbase + 5 * ATILE_B, tid);
    CP_COMMIT();
    const __half* kpf = kv0 + (size_t)128 * D_MODEL;   // prefetch cursors (tile kt+2)
    const __half* vpf = vv0 + (size_t)128 * D_MODEL;

    for (int kt4 = 0; kt4 < 8; kt4++) {
        #pragma unroll
        for (int su = 0; su < 4; su++) {
            const int kt = kt4 * 4 + su;
            if (kt + 2 < 32) {
                attn_load_kv(kpf, vpf,
                             sbase + (uint32_t)(((su + 2) & 3)) * ATILE_B,
                             sbase + (uint32_t)(4 + ((su + 2) & 3)) * ATILE_B, tid);
                kpf += (size_t)64 * D_MODEL;
                vpf += (size_t)64 * D_MODEL;
            }
            CP_COMMIT();
            CP_WAIT(2);
            __syncthreads();

            const uint32_t koff = (uint32_t)su * ATILE_B;

            // S = Q * K^T : sc[nf] covers key cols nf*8..nf*8+7
            float sc[8][4];
            #pragma unroll
            for (int nf = 0; nf < 8; nf++)
                #pragma unroll
                for (int r = 0; r < 4; r++) sc[nf][r] = 0.0f;
            #pragma unroll
            for (int ks = 0; ks < 4; ks++) {            // d16 blocks
                #pragma unroll
                for (int nb = 0; nb < 4; nb++) {        // key n16 blocks
                    uint32_t b[4];
                    ldsm4(b, kbase + koff + (uint32_t)(nb * 16 * AK_STRB + ks * 32));
                    mma_f16(sc[2 * nb],     qa[ks], b);
                    mma_f16(sc[2 * nb + 1], qa[ks], b + 2);
                }
            }

            // online softmax per row-half; exponentials written back into sc
            #pragma unroll
            for (int h = 0; h < 2; h++) {
                float mx = mrun[h];
                #pragma unroll
                for (int nf = 0; nf < 8; nf++)
                    mx = fmaxf(mx, fmaxf(sc[nf][2 * h], sc[nf][2 * h + 1]));
                mx = fmaxf(mx, __shfl_xor_sync(0xffffffffu, mx, 1));
                mx = fmaxf(mx, __shfl_xor_sync(0xffffffffu, mx, 2));
                float corr = ex2(mrun[h] - mx);
                float rs = 0.0f;
                #pragma unroll
                for (int nf = 0; nf < 8; nf++) {
                    float e0 = ex2(sc[nf][2 * h] - mx);
                    float e1 = ex2(sc[nf][2 * h + 1] - mx);
                    sc[nf][2 * h] = e0;
                    sc[nf][2 * h + 1] = e1;
                    rs += e0 + e1;
                }
                rs += __shfl_xor_sync(0xffffffffu, rs, 1);
                rs += __shfl_xor_sync(0xffffffffu, rs, 2);
                lrun[h] = lrun[h] * corr + rs;
                mrun[h] = mx;
                #pragma unroll
                for (int nf = 0; nf < 8; nf++) {
                    o[nf][2 * h]     *= corr;
                    o[nf][2 * h + 1] *= corr;
                }
            }

            // O += P * V : P fragments packed from sc in registers (no smem)
            #pragma unroll
            for (int ks = 0; ks < 4; ks++) {            // s16 blocks
                uint32_t pa[4];
                pa[0] = pack_h2(sc[2 * ks][0],     sc[2 * ks][1]);
                pa[1] = pack_h2(sc[2 * ks][2],     sc[2 * ks][3]);
                pa[2] = pack_h2(sc[2 * ks + 1][0], sc[2 * ks + 1][1]);
                pa[3] = pack_h2(sc[2 * ks + 1][2], sc[2 * ks + 1][3]);
                #pragma unroll
                for (int nb = 0; nb < 4; nb++) {        // d16 blocks
                    uint32_t b[4];
                    ldsm4t(b, vbase + koff + (uint32_t)(ks * 16 * AK_STRB + nb * 32));
                    mma_f16(o[2 * nb],     pa, b);
                    mma_f16(o[2 * nb + 1], pa, b + 2);
                }
            }
            // no trailing barrier: 4-stage + distance-2 prefetch covers it
        }
    }

    // epilogue: normalize, write ctx as half
    #pragma unroll
    for (int h = 0; h < 2; h++) {
        const int row = q0 + warp * 16 + g + 8 * h;
        const float inv = 1.0f / lrun[h];
        __half* op = Out + boff + (size_t)row * D_MODEL + hoff;
        #pragma unroll
        for (int nf = 0; nf < 8; nf++) {
            *(uint32_t*)(op + nf * 8 + 2 * t) =
                pack_h2(o[nf][2 * h] * inv, o[nf][2 * h + 1] * inv);
        }
    }
}

// ---------------- launch -------------------------------------------------
extern "C" void kernel_launch(void* const* d_in, const int* in_sizes, int n_in,
                              void* d_out, int out_size)
{
    const float* x  = (const float*)d_in[0];
    const float* Wq = (const float*)d_in[1];
    const float* bq = (const float*)d_in[2];
    const float* Wk = (const float*)d_in[3];
    const float* bk = (const float*)d_in[4];
    const float* Wv = (const float*)d_in[5];
    const float* bv = (const float*)d_in[6];
    const float* Wo = (const float*)d_in[7];
    const float* bo = (const float*)d_in[8];
    float* out = (float*)d_out;

    __half *xh, *qh, *kh, *vh, *ctxh, *wth;
    cudaGetSymbolAddress((void**)&xh,   g_xh);
    cudaGetSymbolAddress((void**)&qh,   g_qh);
    cudaGetSymbolAddress((void**)&kh,   g_kh);
    cudaGetSymbolAddress((void**)&vh,   g_vh);
    cudaGetSymbolAddress((void**)&ctxh, g_ctxh);
    cudaGetSymbolAddress((void**)&wth,  g_wth);

    cudaFuncSetAttribute(qkv_gemm_kernel, cudaFuncAttributeMaxDynamicSharedMemorySize, GEMM_SMEM_BYTES);
    cudaFuncSetAttribute(out_gemm_kernel, cudaFuncAttributeMaxDynamicSharedMemorySize, GEMM_SMEM_BYTES);
    cudaFuncSetAttribute(attn_mma_kernel, cudaFuncAttributeMaxDynamicSharedMemorySize, ATTN_SMEM_BYTES);

    round_x_kernel<<<(M_TOTAL * D_MODEL) / (256 * 8), 256>>>(x, xh);

    dim3 tgrid(D_MODEL / 32, D_MODEL / 32, 4);
    transpose4_kernel<<<tgrid, 256>>>(Wq, Wk, Wv, Wo, wth);

    dim3 qkvgrid(3 * D_MODEL / 128, M_TOTAL / 128);  // (24, 32)
    qkv_gemm_kernel<<<qkvgrid, 256, GEMM_SMEM_BYTES>>>(xh, wth, bq, bk, bv, qh, kh, vh);

    dim3 agrid(S_LEN / 128, N_HEADS, BATCH);         // (16, 16, 2)
    attn_mma_kernel<<<agrid, 256, ATTN_SMEM_BYTES>>>(qh, kh, vh, ctxh);

    dim3 ogrid(D_MODEL / 128, M_TOTAL / 128);        // (8, 32)
    out_gemm_kernel<<<ogrid, 256, GEMM_SMEM_BYTES>>>(ctxh, wth + 3 * DD, bo, out);
}